// round 1
// baseline (speedup 1.0000x reference)
#include <cuda_runtime.h>
#include <math.h>

#define B_   8
#define T_   1024
#define C_   768
#define H_   12
#define D_   64
#define C3_  2304

// Scratch buffers (no allocation allowed; __device__ globals are the sanctioned path)
__device__ float g_qkv[(size_t)B_ * T_ * C3_];   // [B,T,3C]
__device__ float g_att[(size_t)B_ * T_ * C_];    // [B,T,C] attention output

// ---------------------------------------------------------------------------
// SGEMM: Cout[M,N] = A[M,K] @ W[K,N] + bias[N]
// 128x128 block tile, BK=16, 256 threads, 8x8 per thread, fp32 FMA.
// Requires M%128==0, N%128==0, K%16==0 (true for all three calls).
// ---------------------------------------------------------------------------
__global__ __launch_bounds__(256) void sgemm_bias_kernel(
    const float* __restrict__ A, const float* __restrict__ W,
    const float* __restrict__ bias, float* __restrict__ Cout,
    int M, int N, int K)
{
    __shared__ float As[16][132];   // A tile transposed: As[k][m], padded
    __shared__ float Bs[16][132];   // W tile natural:    Bs[k][n], padded

    const int tid = threadIdx.x;
    const int tx  = tid & 15;       // 0..15 -> n
    const int ty  = tid >> 4;       // 0..15 -> m
    const int rowBase = blockIdx.y * 128;
    const int colBase = blockIdx.x * 128;

    float acc[8][8];
    #pragma unroll
    for (int i = 0; i < 8; i++)
        #pragma unroll
        for (int j = 0; j < 8; j++) acc[i][j] = 0.f;

    for (int k0 = 0; k0 < K; k0 += 16) {
        // Load A tile (128 rows x 16 cols) as float4, store transposed
        #pragma unroll
        for (int l = 0; l < 2; l++) {
            int linear = tid + l * 256;           // 0..511
            int r  = linear >> 2;                 // 0..127
            int kq = (linear & 3) << 2;           // 0,4,8,12
            float4 v = *(const float4*)(A + (size_t)(rowBase + r) * K + k0 + kq);
            As[kq + 0][r] = v.x;
            As[kq + 1][r] = v.y;
            As[kq + 2][r] = v.z;
            As[kq + 3][r] = v.w;
        }
        // Load W tile (16 rows x 128 cols) as float4, natural layout
        #pragma unroll
        for (int l = 0; l < 2; l++) {
            int linear = tid + l * 256;
            int rk = linear >> 5;                 // 0..15
            int c4 = (linear & 31) << 2;          // 0..124
            *(float4*)&Bs[rk][c4] =
                *(const float4*)(W + (size_t)(k0 + rk) * N + colBase + c4);
        }
        __syncthreads();

        #pragma unroll
        for (int k = 0; k < 16; k++) {
            float a[8], b[8];
            *(float4*)&a[0] = *(const float4*)&As[k][ty * 8];
            *(float4*)&a[4] = *(const float4*)&As[k][ty * 8 + 4];
            *(float4*)&b[0] = *(const float4*)&Bs[k][tx * 8];
            *(float4*)&b[4] = *(const float4*)&Bs[k][tx * 8 + 4];
            #pragma unroll
            for (int i = 0; i < 8; i++)
                #pragma unroll
                for (int j = 0; j < 8; j++)
                    acc[i][j] = fmaf(a[i], b[j], acc[i][j]);
        }
        __syncthreads();
    }

    // Epilogue with bias
    #pragma unroll
    for (int i = 0; i < 8; i++) {
        int row = rowBase + ty * 8 + i;
        #pragma unroll
        for (int j4 = 0; j4 < 8; j4 += 4) {
            int col = colBase + tx * 8 + j4;
            float4 o;
            o.x = acc[i][j4 + 0] + bias[col + 0];
            o.y = acc[i][j4 + 1] + bias[col + 1];
            o.z = acc[i][j4 + 2] + bias[col + 2];
            o.w = acc[i][j4 + 3] + bias[col + 3];
            *(float4*)(Cout + (size_t)row * N + col) = o;
        }
    }
}

// ---------------------------------------------------------------------------
// Flash-style causal attention, fp32.
// Grid: (T/64, B*H). Block: 256 threads = 16x16; each thread owns a 4x4
// micro-tile of the 64x64 S / O tiles.
// Q,K stored d-major in smem with XOR swizzle (conflict-free transposed
// writes and reads). V shares the K buffer (loaded after S is consumed).
// ---------------------------------------------------------------------------
__global__ __launch_bounds__(256) void attn_kernel(
    const float* __restrict__ qkv, float* __restrict__ outp)
{
    __shared__ float Qs[64 * 64];    // Qs[d*64 + (t ^ (d&31))]
    __shared__ float KVs[64 * 64];   // K: swizzled d-major; V: natural [k][d]
    __shared__ float Ss[64 * 64];    // P tile [row][k]

    const int tid = threadIdx.x;
    const int tx  = tid & 15;
    const int ty  = tid >> 4;
    const int i0  = ty * 4;          // query rows owned
    const int j0  = tx * 4;          // key cols / d cols owned

    const int bh = blockIdx.y;
    const int b  = bh / H_;
    const int h  = bh % H_;
    const int qt = blockIdx.x;
    const int qBase = qt * 64;

    const float* qptr = qkv + (size_t)b * T_ * C3_ + h * D_;
    const float* kptr = qptr + C_;
    const float* vptr = qptr + 2 * C_;

    // Load Q tile, transposed + swizzled (coalesced gmem, conflict-free smem)
    #pragma unroll
    for (int l = 0; l < 16; l++) {
        int linear = tid + l * 256;        // 0..4095
        int t = linear >> 6;               // local query row
        int d = linear & 63;
        Qs[d * 64 + (t ^ (d & 31))] = qptr[(size_t)(qBase + t) * C3_ + d];
    }

    float m[4], lsum[4], o[4][4];
    #pragma unroll
    for (int i = 0; i < 4; i++) {
        m[i] = -1e30f;
        lsum[i] = 0.f;
        #pragma unroll
        for (int j = 0; j < 4; j++) o[i][j] = 0.f;
    }

    const float scale = 0.125f;   // 1/sqrt(64)

    for (int kt = 0; kt <= qt; kt++) {
        const int kBase = kt * 64;

        __syncthreads();   // previous tile's P@V done before KVs overwrite
        // Load K tile transposed + swizzled
        #pragma unroll
        for (int l = 0; l < 16; l++) {
            int linear = tid + l * 256;
            int t = linear >> 6;
            int d = linear & 63;
            KVs[d * 64 + (t ^ (d & 31))] = kptr[(size_t)(kBase + t) * C3_ + d];
        }
        __syncthreads();

        // S = Q @ K^T  (4x4 per thread over d=0..63)
        float s[4][4];
        #pragma unroll
        for (int i = 0; i < 4; i++)
            #pragma unroll
            for (int j = 0; j < 4; j++) s[i][j] = 0.f;

        #pragma unroll 16
        for (int d = 0; d < 64; d++) {
            const int sw = d & 31;
            const int db = d * 64;
            float qa[4], kb[4];
            #pragma unroll
            for (int i = 0; i < 4; i++) qa[i] = Qs[db + ((i0 + i) ^ sw)];
            #pragma unroll
            for (int j = 0; j < 4; j++) kb[j] = KVs[db + ((j0 + j) ^ sw)];
            #pragma unroll
            for (int i = 0; i < 4; i++)
                #pragma unroll
                for (int j = 0; j < 4; j++)
                    s[i][j] = fmaf(qa[i], kb[j], s[i][j]);
        }

        // scale + causal mask (only the diagonal tile needs masking)
        #pragma unroll
        for (int i = 0; i < 4; i++)
            #pragma unroll
            for (int j = 0; j < 4; j++) {
                s[i][j] *= scale;
                if (kt == qt && (j0 + j) > (i0 + i)) s[i][j] = -1e30f;
            }

        // Online softmax update. Row owned by 16 lanes (same ty) — xor-shuffle
        // over offsets 8,4,2,1 stays within the 16-lane group.
        #pragma unroll
        for (int i = 0; i < 4; i++) {
            float mt = fmaxf(fmaxf(s[i][0], s[i][1]), fmaxf(s[i][2], s[i][3]));
            #pragma unroll
            for (int off = 8; off >= 1; off >>= 1)
                mt = fmaxf(mt, __shfl_xor_sync(0xffffffffu, mt, off));
            float mn = fmaxf(m[i], mt);
            float alpha = __expf(m[i] - mn);
            m[i] = mn;
            float rs = 0.f;
            #pragma unroll
            for (int j = 0; j < 4; j++) {
                s[i][j] = __expf(s[i][j] - mn);
                rs += s[i][j];
            }
            #pragma unroll
            for (int off = 8; off >= 1; off >>= 1)
                rs += __shfl_xor_sync(0xffffffffu, rs, off);
            lsum[i] = lsum[i] * alpha + rs;
            #pragma unroll
            for (int j = 0; j < 4; j++) o[i][j] *= alpha;
        }

        // Stage P into smem for the P@V GEMM
        #pragma unroll
        for (int i = 0; i < 4; i++) {
            float4 p4 = make_float4(s[i][0], s[i][1], s[i][2], s[i][3]);
            *(float4*)&Ss[(i0 + i) * 64 + j0] = p4;
        }
        __syncthreads();   // P written; everyone done reading KVs(K)

        // Load V tile (natural [k][d] layout) into KVs
        #pragma unroll
        for (int l = 0; l < 16; l++) {
            int linear = tid + l * 256;
            int t = linear >> 6;
            int d = linear & 63;
            KVs[t * 64 + d] = vptr[(size_t)(kBase + t) * C3_ + d];
        }
        __syncthreads();

        // O += P @ V
        #pragma unroll 8
        for (int k = 0; k < 64; k++) {
            float4 v4 = *(const float4*)&KVs[k * 64 + j0];
            #pragma unroll
            for (int i = 0; i < 4; i++) {
                float p = Ss[(i0 + i) * 64 + k];
                o[i][0] = fmaf(p, v4.x, o[i][0]);
                o[i][1] = fmaf(p, v4.y, o[i][1]);
                o[i][2] = fmaf(p, v4.z, o[i][2]);
                o[i][3] = fmaf(p, v4.w, o[i][3]);
            }
        }
    }

    // Epilogue: normalize and write [B,T,C] with heads re-interleaved
    #pragma unroll
    for (int i = 0; i < 4; i++) {
        float inv = 1.f / lsum[i];
        int t = qBase + i0 + i;
        float4 r = make_float4(o[i][0] * inv, o[i][1] * inv,
                               o[i][2] * inv, o[i][3] * inv);
        *(float4*)(outp + ((size_t)b * T_ + t) * C_ + h * D_ + j0) = r;
    }
}

// ---------------------------------------------------------------------------
extern "C" void kernel_launch(void* const* d_in, const int* in_sizes, int n_in,
                              void* d_out, int out_size)
{
    (void)in_sizes; (void)n_in; (void)out_size;
    const float* x      = (const float*)d_in[0];
    const float* w_attn = (const float*)d_in[1];
    const float* b_attn = (const float*)d_in[2];
    const float* w_proj = (const float*)d_in[3];
    const float* b_proj = (const float*)d_in[4];
    float* out = (float*)d_out;

    float *qkv = nullptr, *att = nullptr;
    cudaGetSymbolAddress((void**)&qkv, g_qkv);
    cudaGetSymbolAddress((void**)&att, g_att);

    // 1) QKV projection: [8192,768] @ [768,2304] + b_attn
    sgemm_bias_kernel<<<dim3(C3_ / 128, (B_ * T_) / 128), 256>>>(
        x, w_attn, b_attn, qkv, B_ * T_, C3_, C_);

    // 2) Causal flash attention
    attn_kernel<<<dim3(T_ / 64, B_ * H_), 256>>>(qkv, att);

    // 3) Output projection: [8192,768] @ [768,768] + b_proj
    sgemm_bias_kernel<<<dim3(C_ / 128, (B_ * T_) / 128), 256>>>(
        att, w_proj, b_proj, out, B_ * T_, C_, C_);
}

// round 2
// speedup vs baseline: 2.8814x; 2.8814x over previous
#include <cuda_runtime.h>
#include <math.h>

#define B_   8
#define T_   1024
#define C_   768
#define H_   12
#define D_   64
#define C3_  2304

__device__ float g_qkv[(size_t)B_ * T_ * C3_];   // [B,T,3C]
__device__ float g_att[(size_t)B_ * T_ * C_];    // [B,T,C]

// ---------------------------------------------------------------------------
// helpers
// ---------------------------------------------------------------------------
__device__ __forceinline__ unsigned f2tf32(float x) {
    unsigned u;
    asm("cvt.rna.tf32.f32 %0, %1;" : "=r"(u) : "f"(x));
    return u;
}

__device__ __forceinline__ void mma_tf32(float c[4],
    unsigned a0, unsigned a1, unsigned a2, unsigned a3,
    unsigned b0, unsigned b1)
{
    asm volatile(
        "mma.sync.aligned.m16n8k8.row.col.f32.tf32.tf32.f32 "
        "{%0,%1,%2,%3}, {%4,%5,%6,%7}, {%8,%9}, {%0,%1,%2,%3};\n"
        : "+f"(c[0]), "+f"(c[1]), "+f"(c[2]), "+f"(c[3])
        : "r"(a0), "r"(a1), "r"(a2), "r"(a3), "r"(b0), "r"(b1));
}

// ---------------------------------------------------------------------------
// TF32 GEMM: Cout[M,N] = A[M,K] @ W[K,N] + bias
// 128x128 tile, BK=16, 256 thr (8 warps, 2m x 4n), warp tile 64x32.
// ---------------------------------------------------------------------------
#define AST 20    // As row stride (16 k + 4 pad)
#define BST 136   // Bs row stride (128 n + 8 pad)

__global__ __launch_bounds__(256) void gemm_tf32(
    const float* __restrict__ A, const float* __restrict__ W,
    const float* __restrict__ bias, float* __restrict__ Cout,
    int M, int N, int K)
{
    __shared__ unsigned As[2][128 * AST];
    __shared__ unsigned Bs[2][16 * BST];

    const int tid  = threadIdx.x;
    const int lane = tid & 31;
    const int wid  = tid >> 5;
    const int wm   = wid >> 2;           // 0..1
    const int wn   = wid & 3;            // 0..3
    const int g    = lane >> 2;          // 0..7
    const int t4   = lane & 3;           // 0..3

    const int rowBase = blockIdx.y * 128;
    const int colBase = blockIdx.x * 128;

    float acc[4][4][4];                  // [mt][nt][4]
    #pragma unroll
    for (int i = 0; i < 4; i++)
        #pragma unroll
        for (int j = 0; j < 4; j++)
            #pragma unroll
            for (int q = 0; q < 4; q++) acc[i][j][q] = 0.f;

    // global-load index precompute
    const int aR0 = (tid * 2 + 0) >> 2, aK0 = (((tid * 2 + 0) & 3) << 2);
    const int aR1 = (tid * 2 + 1) >> 2, aK1 = (((tid * 2 + 1) & 3) << 2);
    const int bR0 = (tid * 2 + 0) >> 5, bC0 = (((tid * 2 + 0) & 31) << 2);
    const int bR1 = (tid * 2 + 1) >> 5, bC1 = (((tid * 2 + 1) & 31) << 2);

    float4 av0, av1, bv0, bv1;
    // preload stage 0
    av0 = *(const float4*)(A + (size_t)(rowBase + aR0) * K + aK0);
    av1 = *(const float4*)(A + (size_t)(rowBase + aR1) * K + aK1);
    bv0 = *(const float4*)(W + (size_t)(bR0) * N + colBase + bC0);
    bv1 = *(const float4*)(W + (size_t)(bR1) * N + colBase + bC1);
    {
        unsigned* a = &As[0][0];
        a[aR0 * AST + aK0 + 0] = f2tf32(av0.x); a[aR0 * AST + aK0 + 1] = f2tf32(av0.y);
        a[aR0 * AST + aK0 + 2] = f2tf32(av0.z); a[aR0 * AST + aK0 + 3] = f2tf32(av0.w);
        a[aR1 * AST + aK1 + 0] = f2tf32(av1.x); a[aR1 * AST + aK1 + 1] = f2tf32(av1.y);
        a[aR1 * AST + aK1 + 2] = f2tf32(av1.z); a[aR1 * AST + aK1 + 3] = f2tf32(av1.w);
        unsigned* bb = &Bs[0][0];
        bb[bR0 * BST + bC0 + 0] = f2tf32(bv0.x); bb[bR0 * BST + bC0 + 1] = f2tf32(bv0.y);
        bb[bR0 * BST + bC0 + 2] = f2tf32(bv0.z); bb[bR0 * BST + bC0 + 3] = f2tf32(bv0.w);
        bb[bR1 * BST + bC1 + 0] = f2tf32(bv1.x); bb[bR1 * BST + bC1 + 1] = f2tf32(bv1.y);
        bb[bR1 * BST + bC1 + 2] = f2tf32(bv1.z); bb[bR1 * BST + bC1 + 3] = f2tf32(bv1.w);
    }
    __syncthreads();

    const int nstage = K / 16;
    for (int s = 0; s < nstage; s++) {
        const int buf = s & 1;
        if (s + 1 < nstage) {
            const int k0 = (s + 1) * 16;
            av0 = *(const float4*)(A + (size_t)(rowBase + aR0) * K + k0 + aK0);
            av1 = *(const float4*)(A + (size_t)(rowBase + aR1) * K + k0 + aK1);
            bv0 = *(const float4*)(W + (size_t)(k0 + bR0) * N + colBase + bC0);
            bv1 = *(const float4*)(W + (size_t)(k0 + bR1) * N + colBase + bC1);
        }

        const unsigned* a = &As[buf][0];
        const unsigned* bb = &Bs[buf][0];
        #pragma unroll
        for (int kb = 0; kb < 16; kb += 8) {
            unsigned af[4][4];
            #pragma unroll
            for (int mt = 0; mt < 4; mt++) {
                int r0 = wm * 64 + mt * 16 + g;
                af[mt][0] = a[(r0    ) * AST + kb + t4];
                af[mt][1] = a[(r0 + 8) * AST + kb + t4];
                af[mt][2] = a[(r0    ) * AST + kb + t4 + 4];
                af[mt][3] = a[(r0 + 8) * AST + kb + t4 + 4];
            }
            unsigned bf[4][2];
            #pragma unroll
            for (int nt = 0; nt < 4; nt++) {
                int c0 = wn * 32 + nt * 8 + g;
                bf[nt][0] = bb[(kb + t4    ) * BST + c0];
                bf[nt][1] = bb[(kb + t4 + 4) * BST + c0];
            }
            #pragma unroll
            for (int mt = 0; mt < 4; mt++)
                #pragma unroll
                for (int nt = 0; nt < 4; nt++)
                    mma_tf32(acc[mt][nt], af[mt][0], af[mt][1], af[mt][2], af[mt][3],
                             bf[nt][0], bf[nt][1]);
        }

        if (s + 1 < nstage) {
            unsigned* aw = &As[buf ^ 1][0];
            aw[aR0 * AST + aK0 + 0] = f2tf32(av0.x); aw[aR0 * AST + aK0 + 1] = f2tf32(av0.y);
            aw[aR0 * AST + aK0 + 2] = f2tf32(av0.z); aw[aR0 * AST + aK0 + 3] = f2tf32(av0.w);
            aw[aR1 * AST + aK1 + 0] = f2tf32(av1.x); aw[aR1 * AST + aK1 + 1] = f2tf32(av1.y);
            aw[aR1 * AST + aK1 + 2] = f2tf32(av1.z); aw[aR1 * AST + aK1 + 3] = f2tf32(av1.w);
            unsigned* bw = &Bs[buf ^ 1][0];
            bw[bR0 * BST + bC0 + 0] = f2tf32(bv0.x); bw[bR0 * BST + bC0 + 1] = f2tf32(bv0.y);
            bw[bR0 * BST + bC0 + 2] = f2tf32(bv0.z); bw[bR0 * BST + bC0 + 3] = f2tf32(bv0.w);
            bw[bR1 * BST + bC1 + 0] = f2tf32(bv1.x); bw[bR1 * BST + bC1 + 1] = f2tf32(bv1.y);
            bw[bR1 * BST + bC1 + 2] = f2tf32(bv1.z); bw[bR1 * BST + bC1 + 3] = f2tf32(bv1.w);
        }
        __syncthreads();
    }

    // epilogue
    #pragma unroll
    for (int mt = 0; mt < 4; mt++) {
        #pragma unroll
        for (int nt = 0; nt < 4; nt++) {
            int r0 = rowBase + wm * 64 + mt * 16 + g;
            int c  = colBase + wn * 32 + nt * 8 + 2 * t4;
            float bx = bias[c], by = bias[c + 1];
            float2 v0 = make_float2(acc[mt][nt][0] + bx, acc[mt][nt][1] + by);
            float2 v1 = make_float2(acc[mt][nt][2] + bx, acc[mt][nt][3] + by);
            *(float2*)(Cout + (size_t)r0 * N + c)       = v0;
            *(float2*)(Cout + (size_t)(r0 + 8) * N + c) = v1;
        }
    }
}

// ---------------------------------------------------------------------------
// Flash causal attention, tf32 mma. 128 threads = 4 warps; each warp owns
// 16 q-rows of a 64-row q tile; key tiles of 32.
// ---------------------------------------------------------------------------
#define QST 68
#define KST 68
#define VST 72
#define PST 36

__global__ __launch_bounds__(128) void attn_tf32(
    const float* __restrict__ qkv, float* __restrict__ outp)
{
    __shared__ unsigned Qs[64 * QST];
    __shared__ unsigned Ks[32 * KST];
    __shared__ unsigned Vs[32 * VST];
    __shared__ unsigned Ps[64 * PST];

    const int tid  = threadIdx.x;
    const int lane = tid & 31;
    const int wid  = tid >> 5;           // 0..3
    const int g    = lane >> 2;
    const int t4   = lane & 3;

    const int bh = blockIdx.y;
    const int b  = bh / H_;
    const int h  = bh % H_;
    const int qt = blockIdx.x;
    const int qBase = qt * 64;

    const float* qptr = qkv + (size_t)b * T_ * C3_ + h * D_;
    const float* kptr = qptr + C_;
    const float* vptr = qptr + 2 * C_;

    // load Q tile (64x64), tf32
    #pragma unroll
    for (int l = 0; l < 8; l++) {
        int idx = tid + l * 128;
        int r = idx >> 4, c4 = (idx & 15) << 2;
        float4 v = *(const float4*)(qptr + (size_t)(qBase + r) * C3_ + c4);
        Qs[r * QST + c4 + 0] = f2tf32(v.x);
        Qs[r * QST + c4 + 1] = f2tf32(v.y);
        Qs[r * QST + c4 + 2] = f2tf32(v.z);
        Qs[r * QST + c4 + 3] = f2tf32(v.w);
    }

    float o[8][4];
    #pragma unroll
    for (int nt = 0; nt < 8; nt++)
        #pragma unroll
        for (int q = 0; q < 4; q++) o[nt][q] = 0.f;
    float m0 = -1e30f, m1 = -1e30f, l0 = 0.f, l1 = 0.f;

    const float scale = 0.125f;
    const int rowL = wid * 16 + g;       // local q row (thread's row0)
    const int row0 = qBase + rowL;
    const int row1 = row0 + 8;

    const int ktmax = 2 * qt + 1;
    for (int kt = 0; kt <= ktmax; kt++) {
        const int kBase = kt * 32;
        const bool domask = (kt >= 2 * qt);

        __syncthreads();   // all warps done with previous Ks/Vs
        #pragma unroll
        for (int l = 0; l < 4; l++) {
            int idx = tid + l * 128;
            int r = idx >> 4, c4 = (idx & 15) << 2;
            float4 kv = *(const float4*)(kptr + (size_t)(kBase + r) * C3_ + c4);
            Ks[r * KST + c4 + 0] = f2tf32(kv.x);
            Ks[r * KST + c4 + 1] = f2tf32(kv.y);
            Ks[r * KST + c4 + 2] = f2tf32(kv.z);
            Ks[r * KST + c4 + 3] = f2tf32(kv.w);
            float4 vv = *(const float4*)(vptr + (size_t)(kBase + r) * C3_ + c4);
            Vs[r * VST + c4 + 0] = f2tf32(vv.x);
            Vs[r * VST + c4 + 1] = f2tf32(vv.y);
            Vs[r * VST + c4 + 2] = f2tf32(vv.z);
            Vs[r * VST + c4 + 3] = f2tf32(vv.w);
        }
        __syncthreads();

        // S = Q @ K^T : warp tile 16 x 32
        float s[4][4];
        #pragma unroll
        for (int nt = 0; nt < 4; nt++)
            #pragma unroll
            for (int q = 0; q < 4; q++) s[nt][q] = 0.f;

        #pragma unroll
        for (int kb = 0; kb < 64; kb += 8) {
            unsigned a0 = Qs[(rowL    ) * QST + kb + t4];
            unsigned a1 = Qs[(rowL + 8) * QST + kb + t4];
            unsigned a2 = Qs[(rowL    ) * QST + kb + t4 + 4];
            unsigned a3 = Qs[(rowL + 8) * QST + kb + t4 + 4];
            #pragma unroll
            for (int nt = 0; nt < 4; nt++) {
                unsigned b0 = Ks[(nt * 8 + g) * KST + kb + t4];
                unsigned b1 = Ks[(nt * 8 + g) * KST + kb + t4 + 4];
                mma_tf32(s[nt], a0, a1, a2, a3, b0, b1);
            }
        }

        // scale + causal mask
        #pragma unroll
        for (int nt = 0; nt < 4; nt++) {
            #pragma unroll
            for (int q = 0; q < 4; q++) {
                s[nt][q] *= scale;
                if (domask) {
                    int col = kBase + nt * 8 + 2 * t4 + (q & 1);
                    int row = (q < 2) ? row0 : row1;
                    if (col > row) s[nt][q] = -1e30f;
                }
            }
        }

        // online softmax (rows row0, row1) — reduce within 4-lane groups
        float mt0 = -1e30f, mt1 = -1e30f;
        #pragma unroll
        for (int nt = 0; nt < 4; nt++) {
            mt0 = fmaxf(mt0, fmaxf(s[nt][0], s[nt][1]));
            mt1 = fmaxf(mt1, fmaxf(s[nt][2], s[nt][3]));
        }
        mt0 = fmaxf(mt0, __shfl_xor_sync(0xffffffffu, mt0, 1));
        mt0 = fmaxf(mt0, __shfl_xor_sync(0xffffffffu, mt0, 2));
        mt1 = fmaxf(mt1, __shfl_xor_sync(0xffffffffu, mt1, 1));
        mt1 = fmaxf(mt1, __shfl_xor_sync(0xffffffffu, mt1, 2));

        float mn0 = fmaxf(m0, mt0), mn1 = fmaxf(m1, mt1);
        float al0 = __expf(m0 - mn0), al1 = __expf(m1 - mn1);
        m0 = mn0; m1 = mn1;

        float rs0 = 0.f, rs1 = 0.f;
        #pragma unroll
        for (int nt = 0; nt < 4; nt++) {
            s[nt][0] = __expf(s[nt][0] - mn0);
            s[nt][1] = __expf(s[nt][1] - mn0);
            s[nt][2] = __expf(s[nt][2] - mn1);
            s[nt][3] = __expf(s[nt][3] - mn1);
            rs0 += s[nt][0] + s[nt][1];
            rs1 += s[nt][2] + s[nt][3];
        }
        rs0 += __shfl_xor_sync(0xffffffffu, rs0, 1);
        rs0 += __shfl_xor_sync(0xffffffffu, rs0, 2);
        rs1 += __shfl_xor_sync(0xffffffffu, rs1, 1);
        rs1 += __shfl_xor_sync(0xffffffffu, rs1, 2);
        l0 = l0 * al0 + rs0;
        l1 = l1 * al1 + rs1;

        #pragma unroll
        for (int nt = 0; nt < 8; nt++) {
            o[nt][0] *= al0; o[nt][1] *= al0;
            o[nt][2] *= al1; o[nt][3] *= al1;
        }

        // stage P -> smem (tf32) for the PV mma
        #pragma unroll
        for (int nt = 0; nt < 4; nt++) {
            int c = nt * 8 + 2 * t4;
            uint2 p0 = make_uint2(f2tf32(s[nt][0]), f2tf32(s[nt][1]));
            uint2 p1 = make_uint2(f2tf32(s[nt][2]), f2tf32(s[nt][3]));
            *(uint2*)&Ps[(rowL    ) * PST + c] = p0;
            *(uint2*)&Ps[(rowL + 8) * PST + c] = p1;
        }
        __syncwarp();

        // O += P @ V
        #pragma unroll
        for (int kb = 0; kb < 32; kb += 8) {
            unsigned a0 = Ps[(rowL    ) * PST + kb + t4];
            unsigned a1 = Ps[(rowL + 8) * PST + kb + t4];
            unsigned a2 = Ps[(rowL    ) * PST + kb + t4 + 4];
            unsigned a3 = Ps[(rowL + 8) * PST + kb + t4 + 4];
            #pragma unroll
            for (int nt = 0; nt < 8; nt++) {
                unsigned b0 = Vs[(kb + t4    ) * VST + nt * 8 + g];
                unsigned b1 = Vs[(kb + t4 + 4) * VST + nt * 8 + g];
                mma_tf32(o[nt], a0, a1, a2, a3, b0, b1);
            }
        }
    }

    // epilogue
    float inv0 = 1.f / l0, inv1 = 1.f / l1;
    #pragma unroll
    for (int nt = 0; nt < 8; nt++) {
        int d = nt * 8 + 2 * t4;
        float2 v0 = make_float2(o[nt][0] * inv0, o[nt][1] * inv0);
        float2 v1 = make_float2(o[nt][2] * inv1, o[nt][3] * inv1);
        *(float2*)(outp + ((size_t)b * T_ + row0) * C_ + h * D_ + d) = v0;
        *(float2*)(outp + ((size_t)b * T_ + row1) * C_ + h * D_ + d) = v1;
    }
}

// ---------------------------------------------------------------------------
extern "C" void kernel_launch(void* const* d_in, const int* in_sizes, int n_in,
                              void* d_out, int out_size)
{
    (void)in_sizes; (void)n_in; (void)out_size;
    const float* x      = (const float*)d_in[0];
    const float* w_attn = (const float*)d_in[1];
    const float* b_attn = (const float*)d_in[2];
    const float* w_proj = (const float*)d_in[3];
    const float* b_proj = (const float*)d_in[4];
    float* out = (float*)d_out;

    float *qkv = nullptr, *att = nullptr;
    cudaGetSymbolAddress((void**)&qkv, g_qkv);
    cudaGetSymbolAddress((void**)&att, g_att);

    gemm_tf32<<<dim3(C3_ / 128, (B_ * T_) / 128), 256>>>(
        x, w_attn, b_attn, qkv, B_ * T_, C3_, C_);

    attn_tf32<<<dim3(T_ / 64, B_ * H_), 128>>>(qkv, att);

    gemm_tf32<<<dim3(C_ / 128, (B_ * T_) / 128), 256>>>(
        att, w_proj, b_proj, out, B_ * T_, C_, C_);
}